// round 7
// baseline (speedup 1.0000x reference)
#include <cuda_runtime.h>
#include <math.h>

// Problem constants
#define TT 512
#define BB 64
#define II 128
#define HH 1024
#define NCTA 128     // CTAs (single wave: 128 <= 148 SMs, 1 CTA/SM)
#define JB 8         // hidden units per CTA (NCTA*JB == HH)

// ---------------- device state (no allocations allowed) ----------------
// __align__(256): float4 loads require 16B alignment; plain float arrays only
// guarantee 4B. Misalignment here would trap (err715).
__device__ __align__(256) float g_h0[2][BB * HH];   // layer-0 state, dbl buffered, [b][k]
__device__ __align__(256) float g_h1[2][BB * HH];   // layer-1 state, dbl buffered, [b][k]
__device__ unsigned g_count = 0;
__device__ volatile unsigned g_gen = 0;

// ---------------- helpers ----------------
union F4U { float4 f; unsigned long long u[2]; };

__device__ __forceinline__ void fma2(unsigned long long& c,
                                     unsigned long long a,
                                     unsigned long long b) {
    // packed fp32x2 FMA (Blackwell FFMA2): 2 MACs/instr, rt_SMSP=2
    asm("fma.rn.f32x2 %0, %1, %2, %0;" : "+l"(c) : "l"(a), "l"(b));
}

__device__ __forceinline__ float unpack_sum(unsigned long long v) {
    float lo, hi;
    asm("mov.b64 {%0, %1}, %2;" : "=f"(lo), "=f"(hi) : "l"(v));
    return lo + hi;
}

// Sense-reversing chip-wide barrier. Safe because all 128 CTAs are co-resident
// (grid 128 <= 148 SMs, 1 CTA/SM by construction). Every pre-barrier access
// (any CTA) happens-before every post-barrier access (any CTA).
__device__ __forceinline__ void grid_bar() {
    __threadfence();
    __syncthreads();
    if (threadIdx.x == 0) {
        unsigned gen = g_gen;
        if (atomicAdd(&g_count, 1u) == (unsigned)(NCTA - 1)) {
            g_count = 0;
            __threadfence();
            g_gen = gen + 1;
        } else {
            while (g_gen == gen) { __nanosleep(64); }
        }
    }
    __syncthreads();
    __threadfence();
}

__device__ __forceinline__ void copy4(float* dst, const float* src, int n) {
    const float4* s = (const float4*)src;
    float4* d = (float4*)dst;
    for (int i = threadIdx.x; i < (n >> 2); i += 256) d[i] = s[i];
}

// One split-K GEMM segment: this lane accumulates
//   acc[j] (+)= sum_{k=0..RG-1} A[b][kbase+k] * W[j][kbase+k]   (k packed as f32x2)
// ap -> A[b][kbase] (global, L2-resident state), wp -> Wsm[0][kbase] (shared,
// row stride WS). W loads are warp-uniform -> conflict-free LDS broadcast.
// A loads are register-pipelined one 16-float chunk ahead; per-lane 64B
// contiguous chunks keep 32B-sector utilization at 100% via L1.
template <int RG>
__device__ __forceinline__ void gemm_seg(const float* __restrict__ ap,
                                         const float* __restrict__ wp,
                                         const int WS,
                                         unsigned long long* __restrict__ acc) {
    F4U A0, A1, A2, A3;
    A0.f = *(const float4*)(ap + 0);
    A1.f = *(const float4*)(ap + 4);
    A2.f = *(const float4*)(ap + 8);
    A3.f = *(const float4*)(ap + 12);
#pragma unroll 2
    for (int r = 0; r < RG; r += 16) {
        F4U c0 = A0, c1 = A1, c2 = A2, c3 = A3;
        if (r + 16 < RG) {
            A0.f = *(const float4*)(ap + r + 16);
            A1.f = *(const float4*)(ap + r + 20);
            A2.f = *(const float4*)(ap + r + 24);
            A3.f = *(const float4*)(ap + r + 28);
        }
#pragma unroll
        for (int j = 0; j < JB; j++) {
            const float* wr = wp + j * WS + r;
            F4U w0, w1;
            w0.f = *(const float4*)(wr);
            w1.f = *(const float4*)(wr + 4);
            fma2(acc[j], c0.u[0], w0.u[0]);
            fma2(acc[j], c0.u[1], w0.u[1]);
            fma2(acc[j], c1.u[0], w1.u[0]);
            fma2(acc[j], c1.u[1], w1.u[1]);
        }
#pragma unroll
        for (int j = 0; j < JB; j++) {
            const float* wr = wp + j * WS + r + 8;
            F4U w2, w3;
            w2.f = *(const float4*)(wr);
            w3.f = *(const float4*)(wr + 4);
            fma2(acc[j], c2.u[0], w2.u[0]);
            fma2(acc[j], c2.u[1], w2.u[1]);
            fma2(acc[j], c3.u[0], w3.u[0]);
            fma2(acc[j], c3.u[1], w3.u[1]);
        }
    }
}

// 256-float segment processed as four 64-float quarters in CTA-rotated order.
// Anti-partition-camping: staggers the instantaneous L2 address across CTAs so
// the lock-step post-barrier broadcast doesn't hammer one LTS partition.
// Pure summation reorder — bitwise-different, numerically ~1e-7 (gate is 1e-3).
__device__ __forceinline__ void gemm256_rot(const float* __restrict__ ap,
                                            const float* __restrict__ wp,
                                            const int rot,
                                            unsigned long long* __restrict__ acc) {
#pragma unroll
    for (int q = 0; q < 4; q++) {
        const int qq = ((q + rot) & 3) * 64;
        gemm_seg<64>(ap + qq, wp + qq, HH, acc);
    }
}

__device__ __forceinline__ void store_red(float* red, const unsigned long long* acc,
                                          int g, int b) {
    float4 v0, v1;
    v0.x = unpack_sum(acc[0]); v0.y = unpack_sum(acc[1]);
    v0.z = unpack_sum(acc[2]); v0.w = unpack_sum(acc[3]);
    v1.x = unpack_sum(acc[4]); v1.y = unpack_sum(acc[5]);
    v1.z = unpack_sum(acc[6]); v1.w = unpack_sum(acc[7]);
    float4* p = (float4*)&red[(g * 64 + b) * 8];
    p[0] = v0;
    p[1] = v1;
}

// fused leaky-tanh update; thread handles (b=ub, j = j0 + 2*jp .. +1)
__device__ __forceinline__ void update_phase(const float* __restrict__ red,
                                             const float* __restrict__ hold,
                                             float* __restrict__ hnew,
                                             float* __restrict__ out,
                                             int t, int L, int j0, int jp, int ub) {
    float2 s = make_float2(0.f, 0.f);
#pragma unroll
    for (int gg = 0; gg < 4; gg++) {
        float2 v = *(const float2*)&red[(gg * 64 + ub) * 8 + jp * 2];
        s.x += v.x;
        s.y += v.y;
    }
    const int jj = j0 + jp * 2;
    float2 ho = *(const float2*)&hold[ub * HH + jj];
    float2 hn;
    hn.x = 0.5f * ho.x + 0.5f * tanhf(s.x);
    hn.y = 0.5f * ho.y + 0.5f * tanhf(s.y);
    *(float2*)&hnew[ub * HH + jj] = hn;
    // streaming store: keep the 256MB trajectory out of L2 (state must stay hit)
    __stcs((float2*)&out[(((size_t)t * BB + ub) * 2 + L) * HH + jj], hn);
}

// ---------------- persistent kernel ----------------
extern "C" __global__ void __launch_bounds__(256, 1)
reservoir_kernel(const float* __restrict__ x,
                 const float* __restrict__ Win0,
                 const float* __restrict__ What0,
                 const float* __restrict__ Win1,
                 const float* __restrict__ What1,
                 float* __restrict__ out) {
    extern __shared__ float sm[];
    float* Wi0 = sm;                         // JB*II   = 1024 floats
    float* Wh0 = sm + 1024;                  // JB*HH   = 8192
    float* Wi1 = sm + 1024 + 8192;           // 8192
    float* Wh1 = sm + 1024 + 2 * 8192;       // 8192
    float* red = sm + 1024 + 3 * 8192;       // 4*64*8 = 2048

    const int tid = threadIdx.x;
    const int cta = blockIdx.x;
    const int j0 = cta * JB;

    // preload this CTA's weight rows into SMEM (rows contiguous in row-major W)
    copy4(Wi0, Win0 + j0 * II, JB * II);
    copy4(Wh0, What0 + j0 * HH, JB * HH);
    copy4(Wi1, Win1 + j0 * HH, JB * HH);
    copy4(Wh1, What1 + j0 * HH, JB * HH);

    // zero initial state (parity 0): 512 floats per CTA per buffer
    {
        int base = cta * 512 + tid * 2;
        *(float2*)&g_h0[0][base] = make_float2(0.f, 0.f);
        *(float2*)&g_h1[0][base] = make_float2(0.f, 0.f);
    }
    grid_bar();  // state zeroed chip-wide; SMEM weights visible per-CTA

    const int warp = tid >> 5, lane = tid & 31;
    // Split-K group, ROTATED per CTA (anti partition-camping, 1KB stagger).
    // Reduction sums all 4 red groups, so any bijective warp->g map is correct.
    const int g = ((warp >> 1) + cta) & 3;
    const int b = ((warp & 1) << 5) + lane;  // batch index 0..63
    const int rot = (cta >> 2) & 3;          // intra-segment quarter rotation
    const int jp = tid & 3, ub = tid >> 2;   // update-phase mapping

    for (int t = 0; t < TT; t++) {
        const int rp = t & 1;
        const float* h0r = g_h0[rp];
        float* h0w = g_h0[rp ^ 1];
        const float* h1r = g_h1[rp];
        float* h1w = g_h1[rp ^ 1];

        // ---------- layer 0: pre = x_t @ Win0^T + h0 @ What0^T ----------
        unsigned long long acc[JB];
#pragma unroll
        for (int j = 0; j < JB; j++) acc[j] = 0ULL;
        gemm_seg<32>(x + (size_t)t * BB * II + b * II + g * 32, Wi0 + g * 32, II, acc);
        gemm256_rot(h0r + b * HH + g * 256, Wh0 + g * 256, rot, acc);
        store_red(red, acc, g, b);
        __syncthreads();
        update_phase(red, h0r, h0w, out, t, 0, j0, jp, ub);

        grid_bar();  // the single chip-wide barrier per step: e0(t) complete

        // ---------- layer 1: pre = e0_t @ Win1^T + h1 @ What1^T ----------
#pragma unroll
        for (int j = 0; j < JB; j++) acc[j] = 0ULL;
        gemm256_rot(h0w + b * HH + g * 256, Wi1 + g * 256, rot, acc);
        gemm256_rot(h1r + b * HH + g * 256, Wh1 + g * 256, rot, acc);
        store_red(red, acc, g, b);
        __syncthreads();
        update_phase(red, h1r, h1w, out, t, 1, j0, jp, ub);
        __syncthreads();  // protect red before next step's stores
    }
}

// ---------------- launch ----------------
extern "C" void kernel_launch(void* const* d_in, const int* in_sizes, int n_in,
                              void* d_out, int out_size) {
    const float* x     = (const float*)d_in[0];
    const float* Win0  = (const float*)d_in[1];
    const float* What0 = (const float*)d_in[2];
    const float* Win1  = (const float*)d_in[3];
    const float* What1 = (const float*)d_in[4];
    float* out = (float*)d_out;

    const int smem_bytes = (1024 + 3 * 8192 + 2048) * (int)sizeof(float);  // 110592
    cudaFuncSetAttribute(reservoir_kernel,
                         cudaFuncAttributeMaxDynamicSharedMemorySize, smem_bytes);
    reservoir_kernel<<<NCTA, 256, smem_bytes>>>(x, Win0, What0, Win1, What1, out);
}

// round 13
// speedup vs baseline: 1.6387x; 1.6387x over previous
#include <cuda_runtime.h>
#include <math.h>

// Problem constants
#define TT 512
#define BB 64
#define II 128
#define HH 1024
#define NCTA 128     // CTAs (single wave: 128 <= 148 SMs, 1 CTA/SM)
#define JB 8         // hidden units per CTA (NCTA*JB == HH)
#define CHUNK 128    // staged k per chunk (64 b x 128 k = 32KB)
#define APAD 132     // padded A-buffer row stride: 132%32=4 -> conflict-free LDS.128
#define NG 8         // split-K groups (one 16-k slice per warp per chunk)
#define NBUF 3       // staging buffers; depth-3 allows ONE sync per chunk (WAR proof below)

// ---------------- device state (no allocations allowed) ----------------
__device__ __align__(256) float g_h0[2][BB * HH];   // layer-0 state, dbl buffered, [b][k]
__device__ __align__(256) float g_h1[2][BB * HH];   // layer-1 state, dbl buffered, [b][k]
__device__ unsigned g_count = 0;
__device__ volatile unsigned g_gen = 0;

// ---------------- helpers ----------------
union F4U { float4 f; unsigned long long u[2]; };

__device__ __forceinline__ void fma2(unsigned long long& c,
                                     unsigned long long a,
                                     unsigned long long b) {
    // packed fp32x2 FMA (Blackwell FFMA2): 2 MACs/instr, rt_SMSP=2
    asm("fma.rn.f32x2 %0, %1, %2, %0;" : "+l"(c) : "l"(a), "l"(b));
}

__device__ __forceinline__ float unpack_sum(unsigned long long v) {
    float lo, hi;
    asm("mov.b64 {%0, %1}, %2;" : "=f"(lo), "=f"(hi) : "l"(v));
    return lo + hi;
}

__device__ __forceinline__ unsigned smem_u32(const void* p) {
    unsigned a;
    asm("{ .reg .u64 t; cvta.to.shared.u64 t, %1; cvt.u32.u64 %0, t; }"
        : "=r"(a) : "l"(p));
    return a;
}

// cp.async 16B .cg: coalesced GMEM->SMEM, bypasses L1 (only ~8KB left anyway)
__device__ __forceinline__ void cp16(unsigned dst, const float* src) {
    asm volatile("cp.async.cg.shared.global [%0], [%1], 16;" :: "r"(dst), "l"(src));
}
#define CP_COMMIT() asm volatile("cp.async.commit_group;" ::: "memory")
#define CP_WAIT(n)  asm volatile("cp.async.wait_group %0;" :: "n"(n) : "memory")

// Sense-reversing chip-wide barrier (all 128 CTAs co-resident, 1/SM).
__device__ __forceinline__ void grid_bar() {
    __threadfence();
    __syncthreads();
    if (threadIdx.x == 0) {
        unsigned gen = g_gen;
        if (atomicAdd(&g_count, 1u) == (unsigned)(NCTA - 1)) {
            g_count = 0;
            __threadfence();
            g_gen = gen + 1;
        } else {
            while (g_gen == gen) { __nanosleep(64); }
        }
    }
    __syncthreads();
    __threadfence();
}

__device__ __forceinline__ void copy4(float* dst, const float* src, int n) {
    const float4* s = (const float4*)src;
    float4* d = (float4*)dst;
    for (int i = threadIdx.x; i < (n >> 2); i += 256) d[i] = s[i];
}

// Per-chunk descriptor: A source (gmem) + W slice (smem) + W row stride.
struct ChunkRef {
    const float* a;   // &A[0][k0], row stride aStride
    int aStride;
    const float* w;   // &Wsm[0][k0], row stride ws
    int ws;
};

// Stage one A chunk [64 b][128 k] GMEM->SMEM, 8 cp.async per thread, coalesced.
__device__ __forceinline__ void stage_chunk(unsigned abuf_u32, const ChunkRef& cr,
                                            int tid) {
#pragma unroll
    for (int i = 0; i < 8; i++) {
        int f = tid + i * 256;          // float4 index 0..2047
        int b = f >> 5;                  // 32 float4 per row
        int kk = (f & 31) << 2;
        cp16(abuf_u32 + (unsigned)((b * APAD + kk) * 4), cr.a + b * cr.aStride + kk);
    }
    CP_COMMIT();
}

// This thread's share of one chunk: 16 k (its warp's slice) x 8 j x 2 b.
// A from padded SMEM (conflict-free LDS.128), W warp-uniform (LDS broadcast).
// Tile balances crossbar (8*4 + 32*1 = 64 cyc/warp/chunk) vs FFMA2 issue.
__device__ __forceinline__ void compute_chunk(const float* __restrict__ ab0,
                                              const float* __restrict__ ab1,
                                              const float* __restrict__ wbase,
                                              const int WS,
                                              unsigned long long* __restrict__ acc) {
#pragma unroll
    for (int kk = 0; kk < 16; kk += 4) {
        F4U a0, a1;
        a0.f = *(const float4*)(ab0 + kk);
        a1.f = *(const float4*)(ab1 + kk);
#pragma unroll
        for (int jj = 0; jj < 8; jj++) {
            F4U w;
            w.f = *(const float4*)(wbase + jj * WS + kk);
            fma2(acc[jj * 2 + 0], a0.u[0], w.u[0]);
            fma2(acc[jj * 2 + 0], a0.u[1], w.u[1]);
            fma2(acc[jj * 2 + 1], a1.u[0], w.u[0]);
            fma2(acc[jj * 2 + 1], a1.u[1], w.u[1]);
        }
    }
}

// Chained staged GEMM over nTot chunk descriptors (one continuous cp.async
// pipeline: no per-GEMM drain). NBUF=3 + single sync per chunk:
//   RAW: CP_WAIT(1) retires this thread's chunk-c group; barrier publishes all.
//   WAR: compute(c,buf) < barrier(c+1) < stage(c+3,buf) on all thread pairs.
template <typename RefFn>
__device__ __forceinline__ void gemm_chain(float* __restrict__ Abuf, unsigned abuf_u32,
                                           RefFn ref, int nTot, int tid, int l, int g,
                                           unsigned long long* __restrict__ acc) {
    const int BUF = 64 * APAD;
    stage_chunk(abuf_u32, ref(0), tid);
    for (int c = 0; c < nTot; c++) {
        if (c + 1 < nTot) {
            stage_chunk(abuf_u32 + (unsigned)(((c + 1) % NBUF) * BUF * 4), ref(c + 1), tid);
            CP_WAIT(1);   // chunk c's group retired (only c+1's may remain)
        } else {
            CP_WAIT(0);
        }
        __syncthreads();  // publish chunk c; also the WAR fence for buf reuse
        const ChunkRef cr = ref(c);
        const float* abase = Abuf + (c % NBUF) * BUF + g * 16;
        compute_chunk(abase + l * APAD, abase + (l + 32) * APAD,
                      cr.w + g * 16, cr.ws, acc);
    }
}

// Write split-K partials: thread (g, l) owns all 8 j for b = l and b = l+32.
__device__ __forceinline__ void store_red(float* red, const unsigned long long* acc,
                                          int g, int l) {
    float4 v0, v1, v2, v3;
    v0.x = unpack_sum(acc[0]);  v0.y = unpack_sum(acc[2]);
    v0.z = unpack_sum(acc[4]);  v0.w = unpack_sum(acc[6]);
    v1.x = unpack_sum(acc[8]);  v1.y = unpack_sum(acc[10]);
    v1.z = unpack_sum(acc[12]); v1.w = unpack_sum(acc[14]);
    v2.x = unpack_sum(acc[1]);  v2.y = unpack_sum(acc[3]);
    v2.z = unpack_sum(acc[5]);  v2.w = unpack_sum(acc[7]);
    v3.x = unpack_sum(acc[9]);  v3.y = unpack_sum(acc[11]);
    v3.z = unpack_sum(acc[13]); v3.w = unpack_sum(acc[15]);
    float4* p0 = (float4*)&red[(g * 64 + l) * 8];
    p0[0] = v0;
    p0[1] = v1;
    float4* p1 = (float4*)&red[(g * 64 + l + 32) * 8];
    p1[0] = v2;
    p1[1] = v3;
}

// fused leaky-tanh update; thread handles (b=ub, j = j0 + 2*jp .. +1)
__device__ __forceinline__ void update_phase(const float* __restrict__ red,
                                             const float* __restrict__ hold,
                                             float* __restrict__ hnew,
                                             float* __restrict__ out,
                                             int t, int L, int j0, int jp, int ub) {
    float2 s = make_float2(0.f, 0.f);
#pragma unroll
    for (int gg = 0; gg < NG; gg++) {
        float2 v = *(const float2*)&red[(gg * 64 + ub) * 8 + jp * 2];
        s.x += v.x;
        s.y += v.y;
    }
    const int jj = j0 + jp * 2;
    float2 ho = *(const float2*)&hold[ub * HH + jj];
    float2 hn;
    hn.x = 0.5f * ho.x + 0.5f * tanhf(s.x);
    hn.y = 0.5f * ho.y + 0.5f * tanhf(s.y);
    *(float2*)&hnew[ub * HH + jj] = hn;
    // streaming store: keep the 256MB trajectory out of L2
    __stcs((float2*)&out[(((size_t)t * BB + ub) * 2 + L) * HH + jj], hn);
}

// ---------------- persistent kernel ----------------
extern "C" __global__ void __launch_bounds__(256, 1)
reservoir_kernel(const float* __restrict__ x,
                 const float* __restrict__ Win0,
                 const float* __restrict__ What0,
                 const float* __restrict__ Win1,
                 const float* __restrict__ What1,
                 float* __restrict__ out) {
    extern __shared__ float sm[];
    float* Abuf = sm;                              // NBUF * 64*APAD = 25344 floats
    float* Wi0 = sm + NBUF * 64 * APAD;            // 1024
    float* Wh0 = Wi0 + JB * II;                    // 8192
    float* Wi1 = Wh0 + JB * HH;                    // 8192
    float* Wh1 = Wi1 + JB * HH;                    // 8192
    float* red = Wh1 + JB * HH;                    // NG*64*8 = 4096
    const unsigned abuf_u32 = smem_u32(Abuf);

    const int tid = threadIdx.x;
    const int cta = blockIdx.x;
    const int j0 = cta * JB;

    // preload this CTA's weight rows into SMEM (rows contiguous in row-major W)
    copy4(Wi0, Win0 + j0 * II, JB * II);
    copy4(Wh0, What0 + j0 * HH, JB * HH);
    copy4(Wi1, Win1 + j0 * HH, JB * HH);
    copy4(Wh1, What1 + j0 * HH, JB * HH);

    // zero initial state (parity 0): 512 floats per CTA per buffer
    {
        int base = cta * 512 + tid * 2;
        *(float2*)&g_h0[0][base] = make_float2(0.f, 0.f);
        *(float2*)&g_h1[0][base] = make_float2(0.f, 0.f);
    }
    grid_bar();  // state zeroed chip-wide; SMEM weights visible per-CTA

    const int warp = tid >> 5, lane = tid & 31;
    const int g = warp;              // split-K slice within chunk (16 k each)
    const int l = lane;              // lane covers b = l and b = l+32
    const int rot = cta & 7;         // per-CTA chunk rotation (anti-camping)
    const int jp = tid & 3, ub = tid >> 2;   // update-phase mapping

    for (int t = 0; t < TT; t++) {
        const int rp = t & 1;
        const float* h0r = g_h0[rp];
        float* h0w = g_h0[rp ^ 1];
        const float* h1r = g_h1[rp];
        float* h1w = g_h1[rp ^ 1];
        const float* xt = x + (size_t)t * BB * II;

        // ---------- layer 0: pre = x_t @ Win0^T + h0 @ What0^T ----------
        // One chained pipeline: chunk 0 = x (II=128 k), chunks 1..8 = h0 (rotated).
        unsigned long long acc[16];
#pragma unroll
        for (int j = 0; j < 16; j++) acc[j] = 0ULL;
        {
            auto ref = [&](int c) -> ChunkRef {
                if (c == 0) return ChunkRef{xt, II, Wi0, II};
                const int cid = ((c - 1) + rot) & 7;
                return ChunkRef{h0r + cid * CHUNK, HH, Wh0 + cid * CHUNK, HH};
            };
            gemm_chain(Abuf, abuf_u32, ref, 9, tid, l, g, acc);
        }
        store_red(red, acc, g, l);
        __syncthreads();
        update_phase(red, h0r, h0w, out, t, 0, j0, jp, ub);

        grid_bar();  // the single chip-wide barrier per step: e0(t) complete

        // ---------- layer 1: pre = e0_t @ Win1^T + h1 @ What1^T ----------
        // One chained pipeline: chunks 0..7 = e0 (Wi1), chunks 8..15 = h1 (Wh1).
#pragma unroll
        for (int j = 0; j < 16; j++) acc[j] = 0ULL;
        {
            auto ref = [&](int c) -> ChunkRef {
                if (c < 8) {
                    const int cid = (c + rot) & 7;
                    return ChunkRef{h0w + cid * CHUNK, HH, Wi1 + cid * CHUNK, HH};
                }
                const int cid = ((c - 8) + rot) & 7;
                return ChunkRef{h1r + cid * CHUNK, HH, Wh1 + cid * CHUNK, HH};
            };
            gemm_chain(Abuf, abuf_u32, ref, 16, tid, l, g, acc);
        }
        store_red(red, acc, g, l);
        __syncthreads();
        update_phase(red, h1r, h1w, out, t, 1, j0, jp, ub);
        __syncthreads();  // protect red before next step's stores
    }
}

// ---------------- launch ----------------
extern "C" void kernel_launch(void* const* d_in, const int* in_sizes, int n_in,
                              void* d_out, int out_size) {
    const float* x     = (const float*)d_in[0];
    const float* Win0  = (const float*)d_in[1];
    const float* What0 = (const float*)d_in[2];
    const float* Win1  = (const float*)d_in[3];
    const float* What1 = (const float*)d_in[4];
    float* out = (float*)d_out;

    // NBUF*64*132 (Abuf) + 25600 (W) + 4096 (red) floats = 220160 bytes (< 227KB cap)
    const int smem_bytes = (NBUF * 64 * APAD + 1024 + 3 * 8192 + 4096) * (int)sizeof(float);
    cudaFuncSetAttribute(reservoir_kernel,
                         cudaFuncAttributeMaxDynamicSharedMemorySize, smem_bytes);
    reservoir_kernel<<<NCTA, 256, smem_bytes>>>(x, Win0, What0, Win1, What1, out);
}